// round 14
// baseline (speedup 1.0000x reference)
#include <cuda_runtime.h>
#include <cstdint>

#define T_LEN 2048
#define F_DIM 32
#define B_TOT 512
#define BT    (B_TOT * T_LEN)          // 1,048,576 rows

typedef unsigned long long U;          // packed f32x2 carrier

// ---------------- scratch (__device__ globals) ------------------------------
__device__ float2 g_gx2[(size_t)BT * 2 * F_DIM];  // [row][role][f] gate-pair preacts (bias in)
__device__ float  g_yx [(size_t)BT * 2 * F_DIM];  // [row][half][f] odd(x) partials (b_lin in half0)

// ---------------- packed fp32x2 helpers ------------------------------------
__device__ __forceinline__ U ffma2(U a, U b, U c) {
    U d; asm("fma.rn.f32x2 %0, %1, %2, %3;" : "=l"(d) : "l"(a), "l"(b), "l"(c));
    return d;
}
__device__ __forceinline__ U add2(U a, U b) {
    U d; asm("add.rn.f32x2 %0, %1, %2;" : "=l"(d) : "l"(a), "l"(b));
    return d;
}
__device__ __forceinline__ U pack2(float lo, float hi) {
    U d; asm("mov.b64 %0, {%1, %2};" : "=l"(d) : "f"(lo), "f"(hi));
    return d;
}
__device__ __forceinline__ float2 unpk(U d) {
    float2 r; asm("mov.b64 {%0, %1}, %2;" : "=f"(r.x), "=f"(r.y) : "l"(d));
    return r;
}
__device__ __forceinline__ float sum4(U a, U b) {
    float2 s = unpk(add2(a, b));
    return s.x + s.y;
}

// ---------------- activations (proven: rel_err 7.9e-7 end-to-end) -----------
__device__ __forceinline__ float tanh_f(float x) {
    float y; asm("tanh.approx.f32 %0, %1;" : "=f"(y) : "f"(x));
    return y;
}
__device__ __forceinline__ float sig_f(float x) {
    return fmaf(tanh_f(0.5f * x), 0.5f, 0.5f);
}
__device__ __forceinline__ float tanh_acc(float x) {   // final output only
    x = fminf(15.0f, fmaxf(-15.0f, x));
    float e = __expf(-2.0f * x);
    return __fdividef(1.0f - e, 1.0f + e);
}

#define NAMED_BAR(id, cnt) \
    asm volatile("bar.sync %0, %1;" :: "r"(id), "r"(cnt) : "memory")

// ============================================================================
// K1: gx2[row][r] = (bias_{2r} + Wih[2r]·x, bias_{2r+1} + Wih[2r+1]·x)
//     yx[row][r]  = sum_{j in [16r,16r+16)} W_lin[f][2j+1]·x_j (+b_lin if r=0)
//   CTA 128 thr = 2 pairs of role-warps; 16-row tiles, tile-strided over all
//   148 SMs (grid 592 @ 4 CTAs/SM), double-buffered.     (unchanged, proven)
// ============================================================================
__global__ void __launch_bounds__(128, 4)
k1_xpre(const float* __restrict__ x,
        const float* __restrict__ W_ih,
        const float* __restrict__ b_ih,
        const float* __restrict__ b_hh,
        const float* __restrict__ W_lin,
        const float* __restrict__ b_lin)
{
    __shared__ __align__(16) float xs[2][16][F_DIM];   // 4KB
    const int tid = threadIdx.x;
    const int w = tid >> 5, f = tid & 31;
    const int pairId = w >> 1, r = w & 1;
    const int g0 = 2 * r;
    const U ZERO = pack2(0.0f, 0.0f);

    U wa[16], wb[16], wo[8];
    {
        const U* pa = (const U*)(W_ih + (size_t)(g0 * 32 + f) * 32);
        const U* pb = (const U*)(W_ih + (size_t)((g0 + 1) * 32 + f) * 32);
#pragma unroll
        for (int k = 0; k < 16; k++) { wa[k] = pa[k]; wb[k] = pb[k]; }
        const float* pl = W_lin + (size_t)f * 64;
#pragma unroll
        for (int k = 0; k < 4; k++) {
            wo[2 * k]     = pack2(pl[32 * r + 8 * k + 1], pl[32 * r + 8 * k + 3]);
            wo[2 * k + 1] = pack2(pl[32 * r + 8 * k + 5], pl[32 * r + 8 * k + 7]);
        }
    }
    const float biasA = b_ih[g0 * 32 + f] + b_hh[g0 * 32 + f];
    const float biasB = b_ih[(g0 + 1) * 32 + f] + b_hh[(g0 + 1) * 32 + f];
    const float biasY = r ? 0.0f : b_lin[f];

    const int NT = BT / 16;                    // 65536 tiles
    const int srid = tid >> 3, sseg = tid & 7;

    int tile = blockIdx.x;
    if (tile < NT) {
        *(ulonglong2*)&xs[0][srid][sseg * 4] =
            *(const ulonglong2*)(x + ((size_t)(tile * 16 + srid) * F_DIM + sseg * 4));
    }
    __syncthreads();

    int cur = 0;
    while (tile < NT) {
        const int ntile = tile + gridDim.x;
        const bool have = (ntile < NT);
        ulonglong2 nxt;
        if (have)
            nxt = *(const ulonglong2*)(x +
                  ((size_t)(ntile * 16 + srid) * F_DIM + sseg * 4));

        const int row0 = tile * 16 + pairId * 8;
#pragma unroll
        for (int rr = 0; rr < 8; rr++) {
            const ulonglong2* xz = (const ulonglong2*)&xs[cur][pairId * 8 + rr][0];
            U q0 = pack2(biasA, 0.f), q1 = ZERO;
            U q2 = pack2(biasB, 0.f), q3 = ZERO;
            U y0 = pack2(biasY, 0.f), y1 = ZERO;
#pragma unroll
            for (int i = 0; i < 8; i++) {
                ulonglong2 v = xz[i];
                q0 = ffma2(wa[2 * i],     v.x, q0);
                q1 = ffma2(wa[2 * i + 1], v.y, q1);
                q2 = ffma2(wb[2 * i],     v.x, q2);
                q3 = ffma2(wb[2 * i + 1], v.y, q3);
            }
#pragma unroll
            for (int k = 0; k < 4; k++) {
                ulonglong2 v = xz[4 * r + k];
                y0 = ffma2(wo[2 * k],     v.x, y0);
                y1 = ffma2(wo[2 * k + 1], v.y, y1);
            }
            const size_t row = (size_t)(row0 + rr);
            g_gx2[(row * 2 + r) * 32 + f] = make_float2(sum4(q0, q1), sum4(q2, q3));
            g_yx [(row * 2 + r) * 32 + f] = sum4(y0, y1);
        }
        if (have)
            *(ulonglong2*)&xs[cur ^ 1][srid][sseg * 4] = nxt;
        __syncthreads();
        cur ^= 1;
        tile = ntile;
    }
}

// ============================================================================
// K2: recurrence. CTA = 8 teams x 2 role-warps (512 thr), grid 64.
//   => 16 warps/SM, 4 warps/SMSP from 4 different FREE-RUNNING teams.
//   role 0: gates i,f ; role 1: gates g,o. Both roles redundantly compute c/h
//   into a PRIVATE h copy (own-write/own-read, syncwarp only). ONE named
//   64-thr barrier per team per step carries only the activations.
// ============================================================================
__global__ void __launch_bounds__(512, 1)
k2_recur(const float* __restrict__ W_hh,
         const float* __restrict__ W_lin,
         float* __restrict__ out)
{
    __shared__ __align__(16) float  hbuf[8][2][F_DIM];       // private h copies
    __shared__ __align__(16) float4 exb[2][8][2][F_DIM];     // parity exchange

    const int tid = threadIdx.x;
    const int w = tid >> 5, f = tid & 31;
    const int lb = w >> 1;            // team (local batch) 0..7
    const int r  = w & 1;             // role
    const int b  = blockIdx.x * 8 + lb;
    const U ZERO = pack2(0.0f, 0.0f);

    // gate weights (gates 2r, 2r+1)
    U wA[16], wB[16];
    {
        const U* pa = (const U*)(W_hh + (size_t)((2 * r) * 32 + f) * 32);
        const U* pb = (const U*)(W_hh + (size_t)((2 * r + 1) * 32 + f) * 32);
#pragma unroll
        for (int k = 0; k < 16; k++) { wA[k] = pa[k]; wB[k] = pb[k]; }
    }
    // out-linear even half: j in [16r, 16r+16)
    U wle[8];
    {
        const float* pl = W_lin + (size_t)f * 64;
#pragma unroll
        for (int k = 0; k < 4; k++) {
            wle[2 * k]     = pack2(pl[32 * r + 8 * k],     pl[32 * r + 8 * k + 2]);
            wle[2 * k + 1] = pack2(pl[32 * r + 8 * k + 4], pl[32 * r + 8 * k + 6]);
        }
    }

    const float2* gxp = g_gx2 + ((size_t)b * T_LEN * 2 + r) * 32 + f;   // +64/t
    const float*  y0p = g_yx  + ((size_t)b * T_LEN * 2 + 0) * 32 + f;   // +64/t
    const float*  y1p = g_yx  + ((size_t)b * T_LEN * 2 + 1) * 32 + f;
    float*        op  = out   + (size_t)b * T_LEN * F_DIM + f;

    float c = 0.0f;
    float2 gxr[4];                    // gx ring: slot t&3 = row t
#pragma unroll
    for (int k = 0; k < 4; k++) gxr[k] = gxp[(size_t)k * 64];
    float y0r[2], y1r[2];             // finalize rings: init rows 2k+1-r
#pragma unroll
    for (int k = 0; k < 2; k++) {
        int row = 2 * k + 1 - r;
        y0r[k] = y0p[(size_t)row * 64];
        y1r[k] = y1p[(size_t)row * 64];
    }

    hbuf[lb][r][f] = 0.0f;
    __syncthreads();

    for (int tb = 0; tb < T_LEN; tb += 4) {
#pragma unroll
        for (int u = 0; u < 4; u++) {
            const int t   = tb + u;
            const int par = t & 1;

            // ===== P1: gate dots + out-even chunk over OWN h copy =====
            const ulonglong2* hz = (const ulonglong2*)&hbuf[lb][r][0];
            float2 gx = gxr[t & 3];
            U qa0 = pack2(gx.x, 0.f), qa1 = ZERO;
            U qb0 = pack2(gx.y, 0.f), qb1 = ZERO;
#pragma unroll
            for (int i = 0; i < 8; i++) {
                ulonglong2 v = hz[i];
                qa0 = ffma2(wA[2 * i],     v.x, qa0);
                qa1 = ffma2(wA[2 * i + 1], v.y, qa1);
                qb0 = ffma2(wB[2 * i],     v.x, qb0);
                qb1 = ffma2(wB[2 * i + 1], v.y, qb1);
            }
            U o0 = ZERO, o1 = ZERO;
#pragma unroll
            for (int k = 0; k < 4; k++) {
                ulonglong2 v = hz[4 * r + k];
                o0 = ffma2(wle[2 * k],     v.x, o0);
                o1 = ffma2(wle[2 * k + 1], v.y, o1);
            }
            float preA = sum4(qa0, qa1);
            float preB = sum4(qb0, qb1);
            float actA = (r == 1) ? tanh_f(preA) : sig_f(preA);  // g : i
            float actB = sig_f(preB);                            // o : f
            float ohs  = sum4(o0, o1);
            exb[par][lb][r][f] = make_float4(actA, actB, ohs, 0.f);

            {   // gx ring refill (4-step cover)
                int pt = t + 4; if (pt > T_LEN - 1) pt = T_LEN - 1;
                gxr[t & 3] = gxp[(size_t)pt * 64];
            }

            NAMED_BAR(lb + 1, 64);    // the only team barrier per step

            // ===== P2: redundant c/h; own h store; alternating finalize =====
            float4 oth = exb[par][lb][r ^ 1][f];
            float gi, gf, gg, go;
            if (r == 0) { gi = actA;  gf = actB;  gg = oth.x; go = oth.y; }
            else        { gi = oth.x; gf = oth.y; gg = actA;  go = actB;  }
            c = gf * c + gi * gg;
            float h = go * tanh_f(c);
            hbuf[lb][r][f] = h;

            if (r == (t & 1)) {
                int k = ((t - 1) >> 1) & 1;
                if (t > 0) {
                    float s = ohs + oth.z + y0r[k] + y1r[k];
                    op[(size_t)(t - 1) * F_DIM] = tanh_acc(s);
                }
                int pt = t + 3; if (pt > T_LEN - 1) pt = T_LEN - 1;
                y0r[k] = y0p[(size_t)pt * 64];
                y1r[k] = y1p[(size_t)pt * 64];
            }

            __syncwarp();   // own hbuf write -> own next-step read
        }
    }

    // ---- epilogue: out_{T-1} over final h (finalizer = role 0) ----
    {
        const ulonglong2* hz = (const ulonglong2*)&hbuf[lb][r][0];
        U o0 = ZERO, o1 = ZERO;
#pragma unroll
        for (int k = 0; k < 4; k++) {
            ulonglong2 v = hz[4 * r + k];
            o0 = ffma2(wle[2 * k],     v.x, o0);
            o1 = ffma2(wle[2 * k + 1], v.y, o1);
        }
        exb[0][lb][r][f] = make_float4(0.f, 0.f, sum4(o0, o1), 0.f);
        __syncthreads();
        if (r == 0) {
            int k = ((T_LEN - 1) >> 1) & 1;   // ring slot holding row T-1
            float s = exb[0][lb][0][f].z + exb[0][lb][1][f].z
                    + y0r[k] + y1r[k];
            op[(size_t)(T_LEN - 1) * F_DIM] = tanh_acc(s);
        }
    }
}

// ============================================================================
extern "C" void kernel_launch(void* const* d_in, const int* in_sizes, int n_in,
                              void* d_out, int out_size)
{
    const float* x     = (const float*)d_in[0];
    const float* W_ih  = (const float*)d_in[1];
    const float* W_hh  = (const float*)d_in[2];
    const float* b_ih  = (const float*)d_in[3];
    const float* b_hh  = (const float*)d_in[4];
    const float* W_lin = (const float*)d_in[5];
    const float* b_lin = (const float*)d_in[6];
    float* out = (float*)d_out;

    k1_xpre<<<592, 128>>>(x, W_ih, b_ih, b_hh, W_lin, b_lin);   // all 148 SMs
    k2_recur<<<B_TOT / 8, 512>>>(W_hh, W_lin, out);             // 64 CTAs, 8 teams each
}

// round 15
// speedup vs baseline: 1.3802x; 1.3802x over previous
#include <cuda_runtime.h>
#include <cstdint>

#define T_LEN 2048
#define F_DIM 32
#define B_TOT 512
#define BT    (B_TOT * T_LEN)          // 1,048,576 rows

typedef unsigned long long U;          // packed f32x2 carrier

// ---------------- scratch (__device__ globals) ------------------------------
__device__ float g_gx4[(size_t)BT * 4 * F_DIM];  // [row][f][gate 0..3]  536MB (bias in)
__device__ float g_yx [(size_t)BT * 2 * F_DIM];  // [row][f][half 0..1]  268MB (b_lin in half0)

// ---------------- packed fp32x2 helpers ------------------------------------
__device__ __forceinline__ U ffma2(U a, U b, U c) {
    U d; asm("fma.rn.f32x2 %0, %1, %2, %3;" : "=l"(d) : "l"(a), "l"(b), "l"(c));
    return d;
}
__device__ __forceinline__ U add2(U a, U b) {
    U d; asm("add.rn.f32x2 %0, %1, %2;" : "=l"(d) : "l"(a), "l"(b));
    return d;
}
__device__ __forceinline__ U pack2(float lo, float hi) {
    U d; asm("mov.b64 %0, {%1, %2};" : "=l"(d) : "f"(lo), "f"(hi));
    return d;
}
__device__ __forceinline__ float2 unpk(U d) {
    float2 r; asm("mov.b64 {%0, %1}, %2;" : "=f"(r.x), "=f"(r.y) : "l"(d));
    return r;
}
__device__ __forceinline__ float sum4(U a, U b) {
    float2 s = unpk(add2(a, b));
    return s.x + s.y;
}

// ---------------- activations (proven: rel_err 7.9e-7 end-to-end) -----------
__device__ __forceinline__ float tanh_f(float x) {
    float y; asm("tanh.approx.f32 %0, %1;" : "=f"(y) : "f"(x));
    return y;
}
__device__ __forceinline__ float sig_f(float x) {
    return fmaf(tanh_f(0.5f * x), 0.5f, 0.5f);
}
__device__ __forceinline__ float tanh_acc(float x) {   // final output only
    x = fminf(15.0f, fmaxf(-15.0f, x));
    float e = __expf(-2.0f * x);
    return __fdividef(1.0f - e, 1.0f + e);
}

// ============================================================================
// K1: per row: gx4[row][f][g] = bias_g + W_ih[g*32+f]·x[row]   (g = 2r, 2r+1)
//     yx[row][f][r] = sum_{j in [16r,16r+16)} W_lin[f][2j+1]·x_j (+b_lin if r=0)
//   CTA 128 thr = 2 pairs of role-warps; 16-row tiles, tile-strided over all
//   148 SMs (grid 592 @ 4 CTAs/SM), double-buffered.  (proven; stores relaid)
// ============================================================================
__global__ void __launch_bounds__(128, 4)
k1_xpre(const float* __restrict__ x,
        const float* __restrict__ W_ih,
        const float* __restrict__ b_ih,
        const float* __restrict__ b_hh,
        const float* __restrict__ W_lin,
        const float* __restrict__ b_lin)
{
    __shared__ __align__(16) float xs[2][16][F_DIM];   // 4KB
    const int tid = threadIdx.x;
    const int w = tid >> 5, f = tid & 31;
    const int pairId = w >> 1, r = w & 1;
    const int g0 = 2 * r;
    const U ZERO = pack2(0.0f, 0.0f);

    U wa[16], wb[16], wo[8];
    {
        const U* pa = (const U*)(W_ih + (size_t)(g0 * 32 + f) * 32);
        const U* pb = (const U*)(W_ih + (size_t)((g0 + 1) * 32 + f) * 32);
#pragma unroll
        for (int k = 0; k < 16; k++) { wa[k] = pa[k]; wb[k] = pb[k]; }
        const float* pl = W_lin + (size_t)f * 64;
#pragma unroll
        for (int k = 0; k < 4; k++) {
            wo[2 * k]     = pack2(pl[32 * r + 8 * k + 1], pl[32 * r + 8 * k + 3]);
            wo[2 * k + 1] = pack2(pl[32 * r + 8 * k + 5], pl[32 * r + 8 * k + 7]);
        }
    }
    const float biasA = b_ih[g0 * 32 + f] + b_hh[g0 * 32 + f];
    const float biasB = b_ih[(g0 + 1) * 32 + f] + b_hh[(g0 + 1) * 32 + f];
    const float biasY = r ? 0.0f : b_lin[f];

    const int NT = BT / 16;                    // 65536 tiles
    const int srid = tid >> 3, sseg = tid & 7;

    int tile = blockIdx.x;
    if (tile < NT) {
        *(ulonglong2*)&xs[0][srid][sseg * 4] =
            *(const ulonglong2*)(x + ((size_t)(tile * 16 + srid) * F_DIM + sseg * 4));
    }
    __syncthreads();

    int cur = 0;
    while (tile < NT) {
        const int ntile = tile + gridDim.x;
        const bool have = (ntile < NT);
        ulonglong2 nxt;
        if (have)
            nxt = *(const ulonglong2*)(x +
                  ((size_t)(ntile * 16 + srid) * F_DIM + sseg * 4));

        const int row0 = tile * 16 + pairId * 8;
#pragma unroll
        for (int rr = 0; rr < 8; rr++) {
            const ulonglong2* xz = (const ulonglong2*)&xs[cur][pairId * 8 + rr][0];
            U q0 = pack2(biasA, 0.f), q1 = ZERO;
            U q2 = pack2(biasB, 0.f), q3 = ZERO;
            U y0 = pack2(biasY, 0.f), y1 = ZERO;
#pragma unroll
            for (int i = 0; i < 8; i++) {
                ulonglong2 v = xz[i];
                q0 = ffma2(wa[2 * i],     v.x, q0);
                q1 = ffma2(wa[2 * i + 1], v.y, q1);
                q2 = ffma2(wb[2 * i],     v.x, q2);
                q3 = ffma2(wb[2 * i + 1], v.y, q3);
            }
#pragma unroll
            for (int k = 0; k < 4; k++) {
                ulonglong2 v = xz[4 * r + k];
                y0 = ffma2(wo[2 * k],     v.x, y0);
                y1 = ffma2(wo[2 * k + 1], v.y, y1);
            }
            const size_t row = (size_t)(row0 + rr);
            // gx4: [row][f][g] — role writes its 2 gates as float2
            *(float2*)&g_gx4[row * 128 + f * 4 + g0] =
                make_float2(sum4(q0, q1), sum4(q2, q3));
            // yx: [row][f][r]
            g_yx[row * 64 + f * 2 + r] = sum4(y0, y1);
        }
        if (have)
            *(ulonglong2*)&xs[cur ^ 1][srid][sseg * 4] = nxt;
        __syncthreads();
        cur ^= 1;
        tile = ntile;
    }
}

// ============================================================================
// K2: recurrence. 1 WARP = 1 BATCH. Lane l owns feature l for all 4 gates and
//   the out-linear even-half of feature l. No barriers, no cross-warp traffic:
//   h round-trips through a private smem row (STS + syncwarp + 8 uniform LDS).
//   grid 128 x 128thr = 512 warps = 512 batches, 1 warp/SMSP.
// ============================================================================
__global__ void __launch_bounds__(128, 1)
k2_recur(const float* __restrict__ W_hh,
         const float* __restrict__ W_lin,
         float* __restrict__ out)
{
    __shared__ __align__(16) float hs[4][F_DIM];

    const int w = threadIdx.x >> 5;
    const int l = threadIdx.x & 31;
    const int b = blockIdx.x * 4 + w;
    const U ZERO = pack2(0.0f, 0.0f);

    // W_hh rows for all 4 gates at feature l: whh[g][k] pairs
    U whh[4][16];
#pragma unroll
    for (int g = 0; g < 4; g++) {
        const U* p = (const U*)(W_hh + (size_t)(g * 32 + l) * 32);
#pragma unroll
        for (int k = 0; k < 16; k++) whh[g][k] = p[k];
    }
    // out-linear even weights for feature l: pair m = (W[l][4m], W[l][4m+2])
    U wlh[16];
    {
        const float* pl = W_lin + (size_t)l * 64;
#pragma unroll
        for (int m = 0; m < 16; m++) wlh[m] = pack2(pl[4 * m], pl[4 * m + 2]);
    }

    const float4* gxp = (const float4*)(g_gx4 + (size_t)b * T_LEN * 128) + l;  // +32/row
    const float2* yxp = (const float2*)(g_yx  + (size_t)b * T_LEN * 64)  + l;  // +32/row
    float*        op  = out + (size_t)b * T_LEN * F_DIM + l;

    float c = 0.0f;
    float4 gxr[4];            // slot t&3 = row t
    float2 yxr[4];            // slot (t-1)&3 used at t; holds row t-1
#pragma unroll
    for (int k = 0; k < 4; k++) gxr[k] = gxp[(size_t)k * 32];
    yxr[0] = yxp[0]; yxr[1] = yxp[32]; yxr[2] = yxp[64]; yxr[3] = yxp[0]; // slot3 junk

    hs[w][l] = 0.0f;
    __syncwarp();

    for (int tb = 0; tb < T_LEN; tb += 4) {
#pragma unroll
        for (int u = 0; u < 4; u++) {
            const int t = tb + u;

            // ---- gate dots + out-even over h_{t-1} (uniform LDS broadcast) ----
            const ulonglong2* hz = (const ulonglong2*)&hs[w][0];
            float4 gx = gxr[t & 3];
            U a00 = pack2(gx.x, 0.f), a01 = ZERO;
            U a10 = pack2(gx.y, 0.f), a11 = ZERO;
            U a20 = pack2(gx.z, 0.f), a21 = ZERO;
            U a30 = pack2(gx.w, 0.f), a31 = ZERO;
            U ol0 = ZERO, ol1 = ZERO;
#pragma unroll
            for (int i = 0; i < 8; i++) {
                ulonglong2 v = hz[i];
                a00 = ffma2(whh[0][2 * i],     v.x, a00);
                a01 = ffma2(whh[0][2 * i + 1], v.y, a01);
                a10 = ffma2(whh[1][2 * i],     v.x, a10);
                a11 = ffma2(whh[1][2 * i + 1], v.y, a11);
                a20 = ffma2(whh[2][2 * i],     v.x, a20);
                a21 = ffma2(whh[2][2 * i + 1], v.y, a21);
                a30 = ffma2(whh[3][2 * i],     v.x, a30);
                a31 = ffma2(whh[3][2 * i + 1], v.y, a31);
                ol0 = ffma2(wlh[2 * i],        v.x, ol0);
                ol1 = ffma2(wlh[2 * i + 1],    v.y, ol1);
            }
            float gi = sig_f (sum4(a00, a01));
            float gf = sig_f (sum4(a10, a11));
            float gg = tanh_f(sum4(a20, a21));
            float go = sig_f (sum4(a30, a31));
            float ohs = sum4(ol0, ol1);

            // ---- ring refills ----
            {
                int pt = t + 4; if (pt > T_LEN - 1) pt = T_LEN - 1;
                gxr[t & 3] = gxp[(size_t)pt * 32];
            }
            float2 yv = yxr[(t - 1) & 3];
            {
                int pt = t + 3; if (pt > T_LEN - 1) pt = T_LEN - 1;
                yxr[(t - 1) & 3] = yxp[(size_t)pt * 32];
            }

            // ---- finish out_{t-1} (uses h_{t-1} just consumed) ----
            if (t > 0)
                op[(size_t)(t - 1) * F_DIM] = tanh_acc(ohs + yv.x + yv.y);

            // ---- lane-local state update ----
            c = gf * c + gi * gg;
            float h = go * tanh_f(c);
            hs[w][l] = h;
            __syncwarp();
        }
    }

    // ---- epilogue: out_{T-1} over final h; yx[T-1] is in slot (T-2)&3 ----
    {
        const ulonglong2* hz = (const ulonglong2*)&hs[w][0];
        U ol0 = ZERO, ol1 = ZERO;
#pragma unroll
        for (int i = 0; i < 8; i++) {
            ulonglong2 v = hz[i];
            ol0 = ffma2(wlh[2 * i],     v.x, ol0);
            ol1 = ffma2(wlh[2 * i + 1], v.y, ol1);
        }
        float2 yv = yxr[(T_LEN - 2) & 3];
        op[(size_t)(T_LEN - 1) * F_DIM] =
            tanh_acc(sum4(ol0, ol1) + yv.x + yv.y);
    }
}

// ============================================================================
extern "C" void kernel_launch(void* const* d_in, const int* in_sizes, int n_in,
                              void* d_out, int out_size)
{
    const float* x     = (const float*)d_in[0];
    const float* W_ih  = (const float*)d_in[1];
    const float* W_hh  = (const float*)d_in[2];
    const float* b_ih  = (const float*)d_in[3];
    const float* b_hh  = (const float*)d_in[4];
    const float* W_lin = (const float*)d_in[5];
    const float* b_lin = (const float*)d_in[6];
    float* out = (float*)d_out;

    k1_xpre<<<592, 128>>>(x, W_ih, b_ih, b_hh, W_lin, b_lin);   // all 148 SMs
    k2_recur<<<B_TOT / 4, 128>>>(W_hh, W_lin, out);             // warp = batch
}

// round 16
// speedup vs baseline: 1.4326x; 1.0380x over previous
#include <cuda_runtime.h>
#include <cstdint>

#define T_LEN 2048
#define F_DIM 32
#define B_TOT 512
#define BT    (B_TOT * T_LEN)          // 1,048,576 rows

typedef unsigned long long U;          // packed f32x2 carrier

// ---------------- scratch (__device__ globals) ------------------------------
__device__ float g_gx4[(size_t)BT * 4 * F_DIM];  // [row][f][gate 0..3]  536MB (bias in)
__device__ float g_yx [(size_t)BT * 2 * F_DIM];  // [row][f][half 0..1]  268MB (b_lin in half0)

// ---------------- packed fp32x2 helpers ------------------------------------
__device__ __forceinline__ U ffma2(U a, U b, U c) {
    U d; asm("fma.rn.f32x2 %0, %1, %2, %3;" : "=l"(d) : "l"(a), "l"(b), "l"(c));
    return d;
}
__device__ __forceinline__ U add2(U a, U b) {
    U d; asm("add.rn.f32x2 %0, %1, %2;" : "=l"(d) : "l"(a), "l"(b));
    return d;
}
__device__ __forceinline__ U pack2(float lo, float hi) {
    U d; asm("mov.b64 %0, {%1, %2};" : "=l"(d) : "f"(lo), "f"(hi));
    return d;
}
__device__ __forceinline__ float2 unpk(U d) {
    float2 r; asm("mov.b64 {%0, %1}, %2;" : "=f"(r.x), "=f"(r.y) : "l"(d));
    return r;
}
__device__ __forceinline__ float sum4(U a, U b) {
    float2 s = unpk(add2(a, b));
    return s.x + s.y;
}

// ---------------- activations (MUFU.TANH; ~1e-6-class per-op error) ---------
__device__ __forceinline__ float tanh_f(float x) {
    float y; asm("tanh.approx.f32 %0, %1;" : "=f"(y) : "f"(x));
    return y;
}
__device__ __forceinline__ float sig_f(float x) {
    return fmaf(tanh_f(0.5f * x), 0.5f, 0.5f);
}

// ============================================================================
// K1: per row: gx4[row][f][g] = bias_g + W_ih[g*32+f]·x[row]   (g = 2r, 2r+1)
//     yx[row][f][r] = sum_{j in [16r,16r+16)} W_lin[f][2j+1]·x_j (+b_lin if r=0)
//   CTA 128 thr = 2 pairs of role-warps; 16-row tiles, tile-strided over all
//   148 SMs (grid 592 @ 4 CTAs/SM), double-buffered.  (unchanged, proven)
// ============================================================================
__global__ void __launch_bounds__(128, 4)
k1_xpre(const float* __restrict__ x,
        const float* __restrict__ W_ih,
        const float* __restrict__ b_ih,
        const float* __restrict__ b_hh,
        const float* __restrict__ W_lin,
        const float* __restrict__ b_lin)
{
    __shared__ __align__(16) float xs[2][16][F_DIM];   // 4KB
    const int tid = threadIdx.x;
    const int w = tid >> 5, f = tid & 31;
    const int pairId = w >> 1, r = w & 1;
    const int g0 = 2 * r;
    const U ZERO = pack2(0.0f, 0.0f);

    U wa[16], wb[16], wo[8];
    {
        const U* pa = (const U*)(W_ih + (size_t)(g0 * 32 + f) * 32);
        const U* pb = (const U*)(W_ih + (size_t)((g0 + 1) * 32 + f) * 32);
#pragma unroll
        for (int k = 0; k < 16; k++) { wa[k] = pa[k]; wb[k] = pb[k]; }
        const float* pl = W_lin + (size_t)f * 64;
#pragma unroll
        for (int k = 0; k < 4; k++) {
            wo[2 * k]     = pack2(pl[32 * r + 8 * k + 1], pl[32 * r + 8 * k + 3]);
            wo[2 * k + 1] = pack2(pl[32 * r + 8 * k + 5], pl[32 * r + 8 * k + 7]);
        }
    }
    const float biasA = b_ih[g0 * 32 + f] + b_hh[g0 * 32 + f];
    const float biasB = b_ih[(g0 + 1) * 32 + f] + b_hh[(g0 + 1) * 32 + f];
    const float biasY = r ? 0.0f : b_lin[f];

    const int NT = BT / 16;                    // 65536 tiles
    const int srid = tid >> 3, sseg = tid & 7;

    int tile = blockIdx.x;
    if (tile < NT) {
        *(ulonglong2*)&xs[0][srid][sseg * 4] =
            *(const ulonglong2*)(x + ((size_t)(tile * 16 + srid) * F_DIM + sseg * 4));
    }
    __syncthreads();

    int cur = 0;
    while (tile < NT) {
        const int ntile = tile + gridDim.x;
        const bool have = (ntile < NT);
        ulonglong2 nxt;
        if (have)
            nxt = *(const ulonglong2*)(x +
                  ((size_t)(ntile * 16 + srid) * F_DIM + sseg * 4));

        const int row0 = tile * 16 + pairId * 8;
#pragma unroll
        for (int rr = 0; rr < 8; rr++) {
            const ulonglong2* xz = (const ulonglong2*)&xs[cur][pairId * 8 + rr][0];
            U q0 = pack2(biasA, 0.f), q1 = ZERO;
            U q2 = pack2(biasB, 0.f), q3 = ZERO;
            U y0 = pack2(biasY, 0.f), y1 = ZERO;
#pragma unroll
            for (int i = 0; i < 8; i++) {
                ulonglong2 v = xz[i];
                q0 = ffma2(wa[2 * i],     v.x, q0);
                q1 = ffma2(wa[2 * i + 1], v.y, q1);
                q2 = ffma2(wb[2 * i],     v.x, q2);
                q3 = ffma2(wb[2 * i + 1], v.y, q3);
            }
#pragma unroll
            for (int k = 0; k < 4; k++) {
                ulonglong2 v = xz[4 * r + k];
                y0 = ffma2(wo[2 * k],     v.x, y0);
                y1 = ffma2(wo[2 * k + 1], v.y, y1);
            }
            const size_t row = (size_t)(row0 + rr);
            *(float2*)&g_gx4[row * 128 + f * 4 + g0] =
                make_float2(sum4(q0, q1), sum4(q2, q3));
            g_yx[row * 64 + f * 2 + r] = sum4(y0, y1);
        }
        if (have)
            *(ulonglong2*)&xs[cur ^ 1][srid][sseg * 4] = nxt;
        __syncthreads();
        cur ^= 1;
        tile = ntile;
    }
}

// ============================================================================
// K2: recurrence. 1 WARP = 1 BATCH, zero barriers (private smem h row).
//   PACKED: CTA = 256 thr = 8 independent batch-warps, grid 64
//   => 8 warps/SM on 64 SMs = 2 warps/SMSP (co-residency fills issue holes).
// ============================================================================
__global__ void __launch_bounds__(256, 1)
k2_recur(const float* __restrict__ W_hh,
         const float* __restrict__ W_lin,
         float* __restrict__ out)
{
    __shared__ __align__(16) float hs[8][F_DIM];

    const int w = threadIdx.x >> 5;
    const int l = threadIdx.x & 31;
    const int b = blockIdx.x * 8 + w;
    const U ZERO = pack2(0.0f, 0.0f);

    // W_hh rows for all 4 gates at feature l
    U whh[4][16];
#pragma unroll
    for (int g = 0; g < 4; g++) {
        const U* p = (const U*)(W_hh + (size_t)(g * 32 + l) * 32);
#pragma unroll
        for (int k = 0; k < 16; k++) whh[g][k] = p[k];
    }
    // out-linear even weights for feature l: pair m = (W[l][4m], W[l][4m+2])
    U wlh[16];
    {
        const float* pl = W_lin + (size_t)l * 64;
#pragma unroll
        for (int m = 0; m < 16; m++) wlh[m] = pack2(pl[4 * m], pl[4 * m + 2]);
    }

    const float4* gxp = (const float4*)(g_gx4 + (size_t)b * T_LEN * 128) + l;  // +32/row
    const float2* yxp = (const float2*)(g_yx  + (size_t)b * T_LEN * 64)  + l;  // +32/row
    float*        op  = out + (size_t)b * T_LEN * F_DIM + l;

    float c = 0.0f;
    float4 gxr[4];            // slot t&3 = row t
    float2 yxr[4];            // slot (t-1)&3 used at t; holds row t-1
#pragma unroll
    for (int k = 0; k < 4; k++) gxr[k] = gxp[(size_t)k * 32];
    yxr[0] = yxp[0]; yxr[1] = yxp[32]; yxr[2] = yxp[64]; yxr[3] = yxp[0]; // slot3 junk

    hs[w][l] = 0.0f;
    __syncwarp();

    for (int tb = 0; tb < T_LEN; tb += 4) {
#pragma unroll
        for (int u = 0; u < 4; u++) {
            const int t = tb + u;

            // ---- gate dots + out-even over h_{t-1} (uniform LDS broadcast) ----
            const ulonglong2* hz = (const ulonglong2*)&hs[w][0];
            float4 gx = gxr[t & 3];
            U a00 = pack2(gx.x, 0.f), a01 = ZERO;
            U a10 = pack2(gx.y, 0.f), a11 = ZERO;
            U a20 = pack2(gx.z, 0.f), a21 = ZERO;
            U a30 = pack2(gx.w, 0.f), a31 = ZERO;
            U ol0 = ZERO, ol1 = ZERO;
#pragma unroll
            for (int i = 0; i < 8; i++) {
                ulonglong2 v = hz[i];
                a00 = ffma2(whh[0][2 * i],     v.x, a00);
                a01 = ffma2(whh[0][2 * i + 1], v.y, a01);
                a10 = ffma2(whh[1][2 * i],     v.x, a10);
                a11 = ffma2(whh[1][2 * i + 1], v.y, a11);
                a20 = ffma2(whh[2][2 * i],     v.x, a20);
                a21 = ffma2(whh[2][2 * i + 1], v.y, a21);
                a30 = ffma2(whh[3][2 * i],     v.x, a30);
                a31 = ffma2(whh[3][2 * i + 1], v.y, a31);
                ol0 = ffma2(wlh[2 * i],        v.x, ol0);
                ol1 = ffma2(wlh[2 * i + 1],    v.y, ol1);
            }
            float gi = sig_f (sum4(a00, a01));
            float gf = sig_f (sum4(a10, a11));
            float gg = tanh_f(sum4(a20, a21));
            float go = sig_f (sum4(a30, a31));
            float ohs = sum4(ol0, ol1);

            // ---- ring refills ----
            {
                int pt = t + 4; if (pt > T_LEN - 1) pt = T_LEN - 1;
                gxr[t & 3] = gxp[(size_t)pt * 32];
            }
            float2 yv = yxr[(t - 1) & 3];
            {
                int pt = t + 3; if (pt > T_LEN - 1) pt = T_LEN - 1;
                yxr[(t - 1) & 3] = yxp[(size_t)pt * 32];
            }

            // ---- finish out_{t-1} (uses h_{t-1} just consumed) ----
            if (t > 0)
                op[(size_t)(t - 1) * F_DIM] = tanh_f(ohs + yv.x + yv.y);

            // ---- lane-local state update ----
            c = gf * c + gi * gg;
            float h = go * tanh_f(c);
            hs[w][l] = h;
            __syncwarp();
        }
    }

    // ---- epilogue: out_{T-1} over final h; yx[T-1] is in slot (T-2)&3 ----
    {
        const ulonglong2* hz = (const ulonglong2*)&hs[w][0];
        U ol0 = ZERO, ol1 = ZERO;
#pragma unroll
        for (int i = 0; i < 8; i++) {
            ulonglong2 v = hz[i];
            ol0 = ffma2(wlh[2 * i],     v.x, ol0);
            ol1 = ffma2(wlh[2 * i + 1], v.y, ol1);
        }
        float2 yv = yxr[(T_LEN - 2) & 3];
        op[(size_t)(T_LEN - 1) * F_DIM] =
            tanh_f(sum4(ol0, ol1) + yv.x + yv.y);
    }
}

// ============================================================================
extern "C" void kernel_launch(void* const* d_in, const int* in_sizes, int n_in,
                              void* d_out, int out_size)
{
    const float* x     = (const float*)d_in[0];
    const float* W_ih  = (const float*)d_in[1];
    const float* W_hh  = (const float*)d_in[2];
    const float* b_ih  = (const float*)d_in[3];
    const float* b_hh  = (const float*)d_in[4];
    const float* W_lin = (const float*)d_in[5];
    const float* b_lin = (const float*)d_in[6];
    float* out = (float*)d_out;

    k1_xpre<<<592, 128>>>(x, W_ih, b_ih, b_hh, W_lin, b_lin);   // all 148 SMs
    k2_recur<<<B_TOT / 8, 256>>>(W_hh, W_lin, out);             // 8 warps/SM on 64 SMs
}